// round 14
// baseline (speedup 1.0000x reference)
#include <cuda_runtime.h>
#include <cuda_bf16.h>
#include <cuda_fp16.h>
#include <cstdint>

#define MM 8192
#define DD 2048
#define NN 8192
#define TOPK 819
#define BANDCAP 192
typedef unsigned short u16;

__device__ double g_partial[4096];
__device__ float  g_scale[2];
__device__ __align__(16) u16   g_X1[(size_t)MM * DD];   // f16 limb1 of x
__device__ __align__(16) u16   g_X2[(size_t)MM * DD];   // f16 limb2 of x
__device__ __align__(16) u16   g_Q1[(size_t)NN * DD];   // ternary W_syn (f16)
__device__ __align__(16) u16   g_Q2[(size_t)DD * NN];   // ternary W_out (f16)
__device__ __align__(16) float g_Z [(size_t)MM * NN];
__device__ __align__(16) u16   g_H1[(size_t)MM * NN];   // hidden (f16)
__device__ __align__(16) float g_XO[(size_t)MM * DD];

__device__ __forceinline__ uint32_t smem_u32(const void* p) {
    uint32_t a;
    asm("{ .reg .u64 t; cvta.to.shared.u64 t, %1; cvt.u32.u64 %0, t; }" : "=r"(a) : "l"(p));
    return a;
}
#define CP_COMMIT() asm volatile("cp.async.commit_group;" ::: "memory")
#define CP_WAIT(n)  asm volatile("cp.async.wait_group %0;" :: "n"(n) : "memory")

__device__ __forceinline__ void ldsm4(uint32_t* r, uint32_t addr) {
    asm volatile("ldmatrix.sync.aligned.m8n8.x4.shared.b16 {%0,%1,%2,%3}, [%4];"
                 : "=r"(r[0]), "=r"(r[1]), "=r"(r[2]), "=r"(r[3]) : "r"(addr));
}
// f16 inputs, fp32 accumulators
__device__ __forceinline__ void mma_f32(float* c, uint32_t a0, uint32_t a1,
                                        uint32_t a2, uint32_t a3,
                                        uint32_t b0, uint32_t b1) {
    asm volatile(
        "mma.sync.aligned.m16n8k16.row.col.f32.f16.f16.f32 "
        "{%0,%1,%2,%3}, {%4,%5,%6,%7}, {%8,%9}, {%0,%1,%2,%3};\n"
        : "+f"(c[0]), "+f"(c[1]), "+f"(c[2]), "+f"(c[3])
        : "r"(a0), "r"(a1), "r"(a2), "r"(a3), "r"(b0), "r"(b1));
}
// f16 inputs, f16 accumulators (candidate 2x-rate path)
__device__ __forceinline__ void mma_f16(uint32_t* c, uint32_t a0, uint32_t a1,
                                        uint32_t a2, uint32_t a3,
                                        uint32_t b0, uint32_t b1) {
    asm volatile(
        "mma.sync.aligned.m16n8k16.row.col.f16.f16.f16.f16 "
        "{%0,%1}, {%2,%3,%4,%5}, {%6,%7}, {%0,%1};\n"
        : "+r"(c[0]), "+r"(c[1])
        : "r"(a0), "r"(a1), "r"(a2), "r"(a3), "r"(b0), "r"(b1));
}

// ---------------- prep (exactly 3 launches before GEMM1) -------------------
__global__ void k_abs2(const float* __restrict__ Wa, const float* __restrict__ Wb) {
    __shared__ double sd[256];
    const int which = blockIdx.y;
    const float* W = which ? Wb : Wa;
    size_t base = (size_t)blockIdx.x * 8192 + threadIdx.x;
    double s = 0.0;
#pragma unroll
    for (int i = 0; i < 32; i++) s += (double)fabsf(W[base + (size_t)i * 256]);
    sd[threadIdx.x] = s; __syncthreads();
    for (int o = 128; o > 0; o >>= 1) {
        if ((int)threadIdx.x < o) sd[threadIdx.x] += sd[threadIdx.x + o];
        __syncthreads();
    }
    if (threadIdx.x == 0) g_partial[which * 2048 + blockIdx.x] = sd[0];
}
__global__ void k_finalize_scales() {
    __shared__ double sd[256];
    for (int w = 0; w < 2; w++) {
        double s = 0.0;
        for (int i = threadIdx.x; i < 2048; i += 256) s += g_partial[w * 2048 + i];
        sd[threadIdx.x] = s; __syncthreads();
        for (int o = 128; o > 0; o >>= 1) {
            if ((int)threadIdx.x < o) sd[threadIdx.x] += sd[threadIdx.x + o];
            __syncthreads();
        }
        if (threadIdx.x == 0) g_scale[w] = (float)(sd[0] / 16777216.0);
        __syncthreads();
    }
}
__device__ __forceinline__ u16 tq1h(float w, float den) {
    float t = __fdiv_rn(w, den);
    float q = fmaxf(-1.0f, fminf(1.0f, rintf(t)));
    return __half_as_ushort(__float2half_rn(q));    // exact -1/0/+1 in f16
}
__global__ void k_prep(const float4* __restrict__ Wa, const float4* __restrict__ Wb,
                       const float4* __restrict__ x) {
    const int part = blockIdx.x >> 14;
    size_t i = ((size_t)(blockIdx.x & 16383)) * 256 + threadIdx.x;
    if (part < 2) {
        const float4* W = part ? Wb : Wa;
        float den = g_scale[part] + 1e-8f;
        float4 w = W[i];
        ushort4 q;
        q.x = tq1h(w.x, den); q.y = tq1h(w.y, den); q.z = tq1h(w.z, den); q.w = tq1h(w.w, den);
        reinterpret_cast<ushort4*>(part ? g_Q2 : g_Q1)[i] = q;
    } else {
        float4 v = x[i];
        float f[4] = {v.x, v.y, v.z, v.w};
        ushort4 p1, p2;
        u16* a1 = &p1.x; u16* a2 = &p2.x;
#pragma unroll
        for (int j = 0; j < 4; j++) {
            __half h1 = __float2half_rn(f[j]);
            float r1 = f[j] - __half2float(h1);
            a1[j] = __half_as_ushort(h1);
            a2[j] = __half_as_ushort(__float2half_rn(r1));
        }
        reinterpret_cast<ushort4*>(g_X1)[i] = p1;
        reinterpret_cast<ushort4*>(g_X2)[i] = p2;
    }
}

// ---------------- pipelined HMMA GEMM, k-step 64, 512 threads ---------------
// CTA 128(m) x 256(n), 16 warps (4m x 4n), warp tile 32x64, k-step 64,
// 3-stage cp.async, 144B-pitch smem rows (conflict-free ldmatrix).
// GID0: limb1 f16->f32acc + limb2 f16->f16acc (exactness via band repair).
// GID1: single f16 limb, f32 acc.
template<int GID, int NLIMB>
__global__ void __launch_bounds__(512) k_gemm_hmma(
    const float* __restrict__ bias, const float* __restrict__ xres) {
    constexpr int AT = 128 * 144;
    constexpr int BT = 256 * 144;
    constexpr int STAGE = NLIMB * AT + BT;
    constexpr int Kdim = (GID == 0) ? DD : NN;
    constexpr int Nout = (GID == 0) ? NN : DD;
    constexpr int steps = Kdim >> 6;

    extern __shared__ char sm[];
    const uint32_t smaddr = smem_u32(sm);
    const int tid = threadIdx.x;
    const int warp = tid >> 5, lane = tid & 31;
    const int wm = warp >> 2, wn = warp & 3;
    const int tr = lane >> 2, tc = lane & 3;
    const int m0 = blockIdx.y * 128, n0 = blockIdx.x * 256;

    const u16* At[2];
    if (GID == 0) { At[0] = g_X1; At[1] = g_X2; }
    else          { At[0] = g_H1; At[1] = g_H1; }
    const u16* Bq = (GID == 0) ? g_Q1 : g_Q2;
    float* Cout = (GID == 0) ? g_Z : g_XO;

    float accF[2][8][4];
#pragma unroll
    for (int a = 0; a < 2; a++)
#pragma unroll
        for (int b = 0; b < 8; b++)
#pragma unroll
            for (int c = 0; c < 4; c++) accF[a][b][c] = 0.0f;
    uint32_t accH[2][8][2];
#pragma unroll
    for (int a = 0; a < 2; a++)
#pragma unroll
        for (int b = 0; b < 8; b++) { accH[a][b][0] = 0u; accH[a][b][1] = 0u; }

    const uint32_t aoff = (uint32_t)((wm * 32 + (lane & 15)) * 144 + ((lane & 16) ? 16 : 0));
    const uint32_t boff = (uint32_t)((wn * 64 + (lane & 7) + ((lane & 16) ? 8 : 0)) * 144 +
                                     ((lane & 8) ? 16 : 0));

#define LOAD_STAGE(stbuf, kkelem)                                                     \
    do {                                                                              \
        _Pragma("unroll")                                                             \
        for (int l = 0; l < NLIMB; l++) {                                             \
            _Pragma("unroll")                                                         \
            for (int j = 0; j < 2; j++) {                                             \
                int c = tid + 512 * j;                                                \
                int row = c >> 3, col = (c & 7) * 16;                                 \
                uint32_t dst = smaddr + (stbuf) * STAGE + l * AT + row * 144 + col;   \
                const char* src = (const char*)(At[l] + (size_t)(m0 + row) * Kdim + (kkelem)) + col; \
                asm volatile("cp.async.cg.shared.global [%0], [%1], 16;" :: "r"(dst), "l"(src) : "memory"); \
            }                                                                         \
        }                                                                             \
        _Pragma("unroll")                                                             \
        for (int j = 0; j < 4; j++) {                                                 \
            int c = tid + 512 * j;                                                    \
            int row = c >> 3, col = (c & 7) * 16;                                     \
            uint32_t dst = smaddr + (stbuf) * STAGE + NLIMB * AT + row * 144 + col;   \
            const char* src = (const char*)(Bq + (size_t)(n0 + row) * Kdim + (kkelem)) + col; \
            asm volatile("cp.async.cg.shared.global [%0], [%1], 16;" :: "r"(dst), "l"(src) : "memory"); \
        }                                                                             \
    } while (0)

#pragma unroll
    for (int st = 0; st < 2; st++) {
        LOAD_STAGE(st, st * 64);
        CP_COMMIT();
    }

    for (int t = 0; t < steps; t++) {
        CP_WAIT(1);
        __syncthreads();
        if (t + 2 < steps) {
            const int st = (t + 2) % 3;
            LOAD_STAGE(st, (t + 2) * 64);
        }
        CP_COMMIT();

        const uint32_t sstage = smaddr + (t % 3) * STAGE;
        const uint32_t sB = sstage + NLIMB * AT;
#pragma unroll
        for (int h = 0; h < 4; h++) {
            uint32_t breg[4][4];
#pragma unroll
            for (int nb = 0; nb < 4; nb++)
                ldsm4(breg[nb], sB + boff + nb * 2304 + h * 32);
            // limb 1: f32 acc
            {
                uint32_t areg[2][4];
#pragma unroll
                for (int mt = 0; mt < 2; mt++)
                    ldsm4(areg[mt], sstage + aoff + mt * 2304 + h * 32);
#pragma unroll
                for (int mt = 0; mt < 2; mt++)
#pragma unroll
                    for (int nt = 0; nt < 8; nt++)
                        mma_f32(accF[mt][nt], areg[mt][0], areg[mt][1], areg[mt][2], areg[mt][3],
                                breg[nt >> 1][(nt & 1) * 2], breg[nt >> 1][(nt & 1) * 2 + 1]);
            }
            // limb 2 (GID0 only): f16 acc
            if (NLIMB == 2) {
                uint32_t areg[2][4];
#pragma unroll
                for (int mt = 0; mt < 2; mt++)
                    ldsm4(areg[mt], sstage + AT + aoff + mt * 2304 + h * 32);
#pragma unroll
                for (int mt = 0; mt < 2; mt++)
#pragma unroll
                    for (int nt = 0; nt < 8; nt++)
                        mma_f16(accH[mt][nt], areg[mt][0], areg[mt][1], areg[mt][2], areg[mt][3],
                                breg[nt >> 1][(nt & 1) * 2], breg[nt >> 1][(nt & 1) * 2 + 1]);
            }
        }
    }
#undef LOAD_STAGE

    const float sc = g_scale[GID];
#pragma unroll
    for (int mt = 0; mt < 2; mt++) {
        int r = m0 + wm * 32 + mt * 16 + tr;
#pragma unroll
        for (int nt = 0; nt < 8; nt++) {
            int n = n0 + wn * 64 + nt * 8 + tc * 2;
            float cf[4] = {accF[mt][nt][0], accF[mt][nt][1], accF[mt][nt][2], accF[mt][nt][3]};
            if (NLIMB == 2) {
                __half2 l0 = *reinterpret_cast<__half2*>(&accH[mt][nt][0]);
                __half2 l1 = *reinterpret_cast<__half2*>(&accH[mt][nt][1]);
                cf[0] += __half2float(l0.x); cf[1] += __half2float(l0.y);
                cf[2] += __half2float(l1.x); cf[3] += __half2float(l1.y);
            }
            float2 bs = *reinterpret_cast<const float2*>(bias + n);
            float2 o0 = make_float2(fmaf(cf[0], sc, bs.x), fmaf(cf[1], sc, bs.y));
            float2 o1 = make_float2(fmaf(cf[2], sc, bs.x), fmaf(cf[3], sc, bs.y));
            if (GID == 1) {
                float2 x0 = *reinterpret_cast<const float2*>(xres + (size_t)r * Nout + n);
                float2 x1 = *reinterpret_cast<const float2*>(xres + (size_t)(r + 8) * Nout + n);
                o0.x += x0.x; o0.y += x0.y; o1.x += x1.x; o1.y += x1.y;
            }
            *reinterpret_cast<float2*>(Cout + (size_t)r * Nout + n)       = o0;
            *reinterpret_cast<float2*>(Cout + (size_t)(r + 8) * Nout + n) = o1;
        }
    }
}

// ------- top-k with banded exact repair + fused hidden (f16) ---------------
__device__ __forceinline__ uint32_t fmap(float f) {
    uint32_t b = __float_as_uint(f);
    return (b & 0x80000000u) ? ~b : (b | 0x80000000u);
}
__device__ __forceinline__ float funmap(uint32_t u) {
    uint32_t bits = (u & 0x80000000u) ? (u ^ 0x80000000u) : ~u;
    return __uint_as_float(bits);
}
__global__ void __launch_bounds__(512) k_topk_repair(const float* __restrict__ x,
                                                     const float* __restrict__ b_syn) {
    __shared__ uint32_t srow[NN];
    __shared__ float    xs[DD];
    __shared__ uint32_t hist[256];
    __shared__ double   bz[BANDCAP];
    __shared__ int      bidx[BANDCAP];
    __shared__ unsigned char binc[BANDCAP];
    __shared__ uint32_t s_prefix, s_kk;
    __shared__ int      s_A, s_cnt;
    const int row = blockIdx.x, tid = threadIdx.x;
    const int warp = tid >> 5, lane = tid & 31;

    const uint4* zp = reinterpret_cast<const uint4*>(g_Z + (size_t)row * NN);
    for (int i = tid; i < NN / 4; i += 512) {
        uint4 v = zp[i];
        srow[i * 4 + 0] = fmap(__uint_as_float(v.x));
        srow[i * 4 + 1] = fmap(__uint_as_float(v.y));
        srow[i * 4 + 2] = fmap(__uint_as_float(v.z));
        srow[i * 4 + 3] = fmap(__uint_as_float(v.w));
    }
    for (int i = tid; i < DD; i += 512) xs[i] = x[(size_t)row * DD + i];
    if (tid == 0) { s_prefix = 0u; s_kk = TOPK; s_A = 0; s_cnt = 0; }
    __syncthreads();

    uint32_t maskhi = 0u;
    for (int b = 3; b >= 0; b--) {
        if (tid < 256) hist[tid] = 0u;
        __syncthreads();
        const uint32_t pref = s_prefix;
        const int sh = 8 * b;
        for (int i = tid; i < NN; i += 512) {
            uint32_t u = srow[i];
            if ((u & maskhi) == pref) atomicAdd(&hist[(u >> sh) & 0xFF], 1u);
        }
        __syncthreads();
        if (tid == 0) {
            uint32_t cum = 0, kk = s_kk; int sel = 0;
            for (int v = 255; v >= 0; v--) {
                uint32_t c = hist[v];
                if (cum + c >= kk) { sel = v; s_kk = kk - cum; break; }
                cum += c;
            }
            s_prefix = pref | ((uint32_t)sel << sh);
        }
        __syncthreads();
        maskhi |= (0xFFu << (8 * b));
    }
    const float th2 = funmap(s_prefix);
    const float thhi = th2 + 3e-3f;
    const float thlo = th2 - 3e-3f;

    for (int i = tid; i < NN; i += 512) {
        float z = funmap(srow[i]);
        if (z > thhi) atomicAdd(&s_A, 1);
        else if (z >= thlo) {
            int p = atomicAdd(&s_cnt, 1);
            if (p < BANDCAP) bidx[p] = i;
        }
    }
    __syncthreads();
    const int cnt = min(s_cnt, BANDCAP);
    const int need = TOPK - s_A;

    const double sc = (double)g_scale[0];
    for (int b = warp; b < cnt; b += 16) {
        const int j = bidx[b];
        const u16* q = g_Q1 + (size_t)j * DD;
        double acc = 0.0;
        for (int k = lane; k < DD; k += 32)
            acc += (double)xs[k] * (double)__half2float(__ushort_as_half(q[k]));
#pragma unroll
        for (int o = 16; o > 0; o >>= 1) acc += __shfl_down_sync(0xffffffffu, acc, o);
        if (lane == 0) bz[b] = acc * sc + (double)b_syn[j];
    }
    __syncthreads();

    for (int b = tid; b < cnt; b += 512) {
        int rank = 0;
        double v = bz[b];
        for (int b2 = 0; b2 < cnt; b2++) rank += (bz[b2] > v);
        binc[b] = (rank < need) ? 1 : 0;
    }
    __syncthreads();

    u16* hrow = g_H1 + (size_t)row * NN;
    for (int i = tid; i < NN / 4; i += 512) {
        ushort4 p;
        u16* a = &p.x;
#pragma unroll
        for (int j = 0; j < 4; j++) {
            float z = funmap(srow[i * 4 + j]);
            float h = (z > thhi) ? fmaxf(z, 0.0f) : 0.0f;
            a[j] = __half_as_ushort(__float2half_rn(h));
        }
        reinterpret_cast<ushort4*>(hrow)[i] = p;
    }
    __syncthreads();
    for (int b = tid; b < cnt; b += 512) {
        int j = bidx[b];
        float z = funmap(srow[j]);
        float h = binc[b] ? fmaxf(z, 0.0f) : 0.0f;
        hrow[j] = __half_as_ushort(__float2half_rn(h));
    }
}

__global__ void k_ln(const float* __restrict__ gamma, const float* __restrict__ beta,
                     float* __restrict__ out) {
    __shared__ float ssum[256], ssq[256];
    const int row = blockIdx.x, t = threadIdx.x;
    const float4* xp = reinterpret_cast<const float4*>(g_XO + (size_t)row * DD);
    float4 v0 = xp[t], v1 = xp[t + 256];
    float s = v0.x + v0.y + v0.z + v0.w + v1.x + v1.y + v1.z + v1.w;
    float q = v0.x * v0.x + v0.y * v0.y + v0.z * v0.z + v0.w * v0.w +
              v1.x * v1.x + v1.y * v1.y + v1.z * v1.z + v1.w * v1.w;
    ssum[t] = s; ssq[t] = q; __syncthreads();
    for (int o = 128; o > 0; o >>= 1) {
        if (t < o) { ssum[t] += ssum[t + o]; ssq[t] += ssq[t + o]; }
        __syncthreads();
    }
    float mu  = ssum[0] * (1.0f / DD);
    float var = ssq[0] * (1.0f / DD) - mu * mu;
    float rs  = rsqrtf(var + 1e-5f);
    const float4* gp = reinterpret_cast<const float4*>(gamma);
    const float4* bp = reinterpret_cast<const float4*>(beta);
    float4 g0 = gp[t], g1 = gp[t + 256];
    float4 b0 = bp[t], b1 = bp[t + 256];
    float4 o0, o1;
    o0.x = (v0.x - mu) * rs * g0.x + b0.x; o0.y = (v0.y - mu) * rs * g0.y + b0.y;
    o0.z = (v0.z - mu) * rs * g0.z + b0.z; o0.w = (v0.w - mu) * rs * g0.w + b0.w;
    o1.x = (v1.x - mu) * rs * g1.x + b1.x; o1.y = (v1.y - mu) * rs * g1.y + b1.y;
    o1.z = (v1.z - mu) * rs * g1.z + b1.z; o1.w = (v1.w - mu) * rs * g1.w + b1.w;
    float4* op = reinterpret_cast<float4*>(out + (size_t)row * DD);
    op[t] = o0; op[t + 256] = o1;
}

// ---------------- launcher --------------------------------------------------
extern "C" void kernel_launch(void* const* d_in, const int* in_sizes, int n_in,
                              void* d_out, int out_size) {
    (void)in_sizes; (void)n_in; (void)out_size;
    const float* x     = (const float*)d_in[0];
    const float* W_syn = (const float*)d_in[1];
    const float* b_syn = (const float*)d_in[2];
    const float* W_out = (const float*)d_in[3];
    const float* b_out = (const float*)d_in[4];
    const float* gamma = (const float*)d_in[5];
    const float* beta  = (const float*)d_in[6];
    float* out = (float*)d_out;

    const int SM1 = 3 * (2 * 18432 + 36864);   // 221184 B
    const int SM2 = 3 * (1 * 18432 + 36864);   // 165888 B
    cudaFuncSetAttribute(k_gemm_hmma<0, 2>, cudaFuncAttributeMaxDynamicSharedMemorySize, SM1);
    cudaFuncSetAttribute(k_gemm_hmma<1, 1>, cudaFuncAttributeMaxDynamicSharedMemorySize, SM2);

    // 3 launches before GEMM1 -> ncu -s 5 -c 1 keeps capturing the GEMM.
    k_abs2<<<dim3(2048, 2), 256>>>(W_syn, W_out);
    k_finalize_scales<<<1, 256>>>();
    k_prep<<<49152, 256>>>((const float4*)W_syn, (const float4*)W_out, (const float4*)x);
    k_gemm_hmma<0, 2><<<dim3(32, 64), 512, SM1>>>(b_syn, nullptr);
    k_topk_repair<<<MM, 512>>>(x, b_syn);
    k_gemm_hmma<1, 1><<<dim3(8, 64), 512, SM2>>>(b_out, x);
    k_ln<<<MM, 256>>>(gamma, beta, out);
}

// round 15
// speedup vs baseline: 1.3946x; 1.3946x over previous
#include <cuda_runtime.h>
#include <cuda_bf16.h>
#include <cuda_fp16.h>
#include <cstdint>

#define MM 8192
#define DD 2048
#define NN 8192
#define TOPK 819
#define BANDCAP 192
typedef unsigned short u16;

__device__ double g_partial[4096];
__device__ float  g_scale[2];
__device__ __align__(16) u16   g_X1[(size_t)MM * DD];   // f16 limb1 of x
__device__ __align__(16) u16   g_X2[(size_t)MM * DD];   // f16 limb2 of x
__device__ __align__(16) u16   g_Q1[(size_t)NN * DD];   // ternary W_syn (f16)
__device__ __align__(16) u16   g_Q2[(size_t)DD * NN];   // ternary W_out (f16)
__device__ __align__(16) float g_Z [(size_t)MM * NN];
__device__ __align__(16) u16   g_H1[(size_t)MM * NN];   // hidden (f16)
__device__ __align__(16) float g_XO[(size_t)MM * DD];

__device__ __forceinline__ uint32_t smem_u32(const void* p) {
    uint32_t a;
    asm("{ .reg .u64 t; cvta.to.shared.u64 t, %1; cvt.u32.u64 %0, t; }" : "=r"(a) : "l"(p));
    return a;
}
#define CP_COMMIT() asm volatile("cp.async.commit_group;" ::: "memory")
#define CP_WAIT(n)  asm volatile("cp.async.wait_group %0;" :: "n"(n) : "memory")

__device__ __forceinline__ void ldsm4(uint32_t* r, uint32_t addr) {
    asm volatile("ldmatrix.sync.aligned.m8n8.x4.shared.b16 {%0,%1,%2,%3}, [%4];"
                 : "=r"(r[0]), "=r"(r[1]), "=r"(r[2]), "=r"(r[3]) : "r"(addr));
}
__device__ __forceinline__ void mma_f32(float* c, uint32_t a0, uint32_t a1,
                                        uint32_t a2, uint32_t a3,
                                        uint32_t b0, uint32_t b1) {
    asm volatile(
        "mma.sync.aligned.m16n8k16.row.col.f32.f16.f16.f32 "
        "{%0,%1,%2,%3}, {%4,%5,%6,%7}, {%8,%9}, {%0,%1,%2,%3};\n"
        : "+f"(c[0]), "+f"(c[1]), "+f"(c[2]), "+f"(c[3])
        : "r"(a0), "r"(a1), "r"(a2), "r"(a3), "r"(b0), "r"(b1));
}

// ---------------- prep (exactly 3 launches before GEMM1) -------------------
__global__ void k_abs2(const float* __restrict__ Wa, const float* __restrict__ Wb) {
    __shared__ double sd[256];
    const int which = blockIdx.y;
    const float* W = which ? Wb : Wa;
    size_t base = (size_t)blockIdx.x * 8192 + threadIdx.x;
    double s = 0.0;
#pragma unroll
    for (int i = 0; i < 32; i++) s += (double)fabsf(W[base + (size_t)i * 256]);
    sd[threadIdx.x] = s; __syncthreads();
    for (int o = 128; o > 0; o >>= 1) {
        if ((int)threadIdx.x < o) sd[threadIdx.x] += sd[threadIdx.x + o];
        __syncthreads();
    }
    if (threadIdx.x == 0) g_partial[which * 2048 + blockIdx.x] = sd[0];
}
__global__ void k_finalize_scales() {
    __shared__ double sd[256];
    for (int w = 0; w < 2; w++) {
        double s = 0.0;
        for (int i = threadIdx.x; i < 2048; i += 256) s += g_partial[w * 2048 + i];
        sd[threadIdx.x] = s; __syncthreads();
        for (int o = 128; o > 0; o >>= 1) {
            if ((int)threadIdx.x < o) sd[threadIdx.x] += sd[threadIdx.x + o];
            __syncthreads();
        }
        if (threadIdx.x == 0) g_scale[w] = (float)(sd[0] / 16777216.0);
        __syncthreads();
    }
}
__device__ __forceinline__ u16 tq1h(float w, float den) {
    float t = __fdiv_rn(w, den);
    float q = fmaxf(-1.0f, fminf(1.0f, rintf(t)));
    return __half_as_ushort(__float2half_rn(q));    // exact -1/0/+1 in f16
}
__global__ void k_prep(const float4* __restrict__ Wa, const float4* __restrict__ Wb,
                       const float4* __restrict__ x) {
    const int part = blockIdx.x >> 14;
    size_t i = ((size_t)(blockIdx.x & 16383)) * 256 + threadIdx.x;
    if (part < 2) {
        const float4* W = part ? Wb : Wa;
        float den = g_scale[part] + 1e-8f;
        float4 w = W[i];
        ushort4 q;
        q.x = tq1h(w.x, den); q.y = tq1h(w.y, den); q.z = tq1h(w.z, den); q.w = tq1h(w.w, den);
        reinterpret_cast<ushort4*>(part ? g_Q2 : g_Q1)[i] = q;
    } else {
        float4 v = x[i];
        float f[4] = {v.x, v.y, v.z, v.w};
        ushort4 p1, p2;
        u16* a1 = &p1.x; u16* a2 = &p2.x;
#pragma unroll
        for (int j = 0; j < 4; j++) {
            __half h1 = __float2half_rn(f[j]);
            float r1 = f[j] - __half2float(h1);
            a1[j] = __half_as_ushort(h1);
            a2[j] = __half_as_ushort(__float2half_rn(r1));
        }
        reinterpret_cast<ushort4*>(g_X1)[i] = p1;
        reinterpret_cast<ushort4*>(g_X2)[i] = p2;
    }
}

// ---------------- pipelined HMMA GEMM, k-step 64, 512 threads ---------------
// CTA 128(m) x 256(n), 16 warps (4m x 4n), warp tile 32x64, k-step 64,
// 3-stage cp.async, 144B-pitch smem rows (conflict-free ldmatrix).
// Both limbs accumulate into the same fp32 accumulators.
template<int GID, int NLIMB>
__global__ void __launch_bounds__(512) k_gemm_hmma(
    const float* __restrict__ bias, const float* __restrict__ xres) {
    constexpr int AT = 128 * 144;
    constexpr int BT = 256 * 144;
    constexpr int STAGE = NLIMB * AT + BT;
    constexpr int Kdim = (GID == 0) ? DD : NN;
    constexpr int Nout = (GID == 0) ? NN : DD;
    constexpr int steps = Kdim >> 6;

    extern __shared__ char sm[];
    const uint32_t smaddr = smem_u32(sm);
    const int tid = threadIdx.x;
    const int warp = tid >> 5, lane = tid & 31;
    const int wm = warp >> 2, wn = warp & 3;
    const int tr = lane >> 2, tc = lane & 3;
    const int m0 = blockIdx.y * 128, n0 = blockIdx.x * 256;

    const u16* At[2];
    if (GID == 0) { At[0] = g_X1; At[1] = g_X2; }
    else          { At[0] = g_H1; At[1] = g_H1; }
    const u16* Bq = (GID == 0) ? g_Q1 : g_Q2;
    float* Cout = (GID == 0) ? g_Z : g_XO;

    float acc[2][8][4];
#pragma unroll
    for (int a = 0; a < 2; a++)
#pragma unroll
        for (int b = 0; b < 8; b++)
#pragma unroll
            for (int c = 0; c < 4; c++) acc[a][b][c] = 0.0f;

    const uint32_t aoff = (uint32_t)((wm * 32 + (lane & 15)) * 144 + ((lane & 16) ? 16 : 0));
    const uint32_t boff = (uint32_t)((wn * 64 + (lane & 7) + ((lane & 16) ? 8 : 0)) * 144 +
                                     ((lane & 8) ? 16 : 0));

#define LOAD_STAGE(stbuf, kkelem)                                                     \
    do {                                                                              \
        _Pragma("unroll")                                                             \
        for (int l = 0; l < NLIMB; l++) {                                             \
            _Pragma("unroll")                                                         \
            for (int j = 0; j < 2; j++) {                                             \
                int c = tid + 512 * j;                                                \
                int row = c >> 3, col = (c & 7) * 16;                                 \
                uint32_t dst = smaddr + (stbuf) * STAGE + l * AT + row * 144 + col;   \
                const char* src = (const char*)(At[l] + (size_t)(m0 + row) * Kdim + (kkelem)) + col; \
                asm volatile("cp.async.cg.shared.global [%0], [%1], 16;" :: "r"(dst), "l"(src) : "memory"); \
            }                                                                         \
        }                                                                             \
        _Pragma("unroll")                                                             \
        for (int j = 0; j < 4; j++) {                                                 \
            int c = tid + 512 * j;                                                    \
            int row = c >> 3, col = (c & 7) * 16;                                     \
            uint32_t dst = smaddr + (stbuf) * STAGE + NLIMB * AT + row * 144 + col;   \
            const char* src = (const char*)(Bq + (size_t)(n0 + row) * Kdim + (kkelem)) + col; \
            asm volatile("cp.async.cg.shared.global [%0], [%1], 16;" :: "r"(dst), "l"(src) : "memory"); \
        }                                                                             \
    } while (0)

#pragma unroll
    for (int st = 0; st < 2; st++) {
        LOAD_STAGE(st, st * 64);
        CP_COMMIT();
    }

    for (int t = 0; t < steps; t++) {
        CP_WAIT(1);
        __syncthreads();
        if (t + 2 < steps) {
            const int st = (t + 2) % 3;
            LOAD_STAGE(st, (t + 2) * 64);
        }
        CP_COMMIT();

        const uint32_t sstage = smaddr + (t % 3) * STAGE;
        const uint32_t sB = sstage + NLIMB * AT;
#pragma unroll
        for (int h = 0; h < 4; h++) {
            uint32_t breg[4][4];
#pragma unroll
            for (int nb = 0; nb < 4; nb++)
                ldsm4(breg[nb], sB + boff + nb * 2304 + h * 32);
#pragma unroll
            for (int l = 0; l < NLIMB; l++) {
                uint32_t areg[2][4];
#pragma unroll
                for (int mt = 0; mt < 2; mt++)
                    ldsm4(areg[mt], sstage + l * AT + aoff + mt * 2304 + h * 32);
#pragma unroll
                for (int mt = 0; mt < 2; mt++)
#pragma unroll
                    for (int nt = 0; nt < 8; nt++)
                        mma_f32(acc[mt][nt], areg[mt][0], areg[mt][1], areg[mt][2], areg[mt][3],
                                breg[nt >> 1][(nt & 1) * 2], breg[nt >> 1][(nt & 1) * 2 + 1]);
            }
        }
    }
#undef LOAD_STAGE

    const float sc = g_scale[GID];
#pragma unroll
    for (int mt = 0; mt < 2; mt++) {
        int r = m0 + wm * 32 + mt * 16 + tr;
#pragma unroll
        for (int nt = 0; nt < 8; nt++) {
            int n = n0 + wn * 64 + nt * 8 + tc * 2;
            float2 bs = *reinterpret_cast<const float2*>(bias + n);
            float2 o0 = make_float2(fmaf(acc[mt][nt][0], sc, bs.x),
                                    fmaf(acc[mt][nt][1], sc, bs.y));
            float2 o1 = make_float2(fmaf(acc[mt][nt][2], sc, bs.x),
                                    fmaf(acc[mt][nt][3], sc, bs.y));
            if (GID == 1) {
                float2 x0 = *reinterpret_cast<const float2*>(xres + (size_t)r * Nout + n);
                float2 x1 = *reinterpret_cast<const float2*>(xres + (size_t)(r + 8) * Nout + n);
                o0.x += x0.x; o0.y += x0.y; o1.x += x1.x; o1.y += x1.y;
            }
            *reinterpret_cast<float2*>(Cout + (size_t)r * Nout + n)       = o0;
            *reinterpret_cast<float2*>(Cout + (size_t)(r + 8) * Nout + n) = o1;
        }
    }
}

// ------- top-k: parallel-scan radix select + fp32-Kahan band repair --------
__device__ __forceinline__ uint32_t fmap(float f) {
    uint32_t b = __float_as_uint(f);
    return (b & 0x80000000u) ? ~b : (b | 0x80000000u);
}
__device__ __forceinline__ float funmap(uint32_t u) {
    uint32_t bits = (u & 0x80000000u) ? (u ^ 0x80000000u) : ~u;
    return __uint_as_float(bits);
}
__global__ void __launch_bounds__(512) k_topk_repair(const float* __restrict__ x,
                                                     const float* __restrict__ b_syn) {
    __shared__ uint32_t srow[NN];
    __shared__ float    xs[DD];
    __shared__ uint32_t hist[256];
    __shared__ double   bz[BANDCAP];
    __shared__ int      bidx[BANDCAP];
    __shared__ unsigned char binc[BANDCAP];
    __shared__ uint32_t s_prefix, s_kk;
    __shared__ int      s_A, s_cnt;
    const int row = blockIdx.x, tid = threadIdx.x;
    const int warp = tid >> 5, lane = tid & 31;

    const uint4* zp = reinterpret_cast<const uint4*>(g_Z + (size_t)row * NN);
    for (int i = tid; i < NN / 4; i += 512) {
        uint4 v = zp[i];
        srow[i * 4 + 0] = fmap(__uint_as_float(v.x));
        srow[i * 4 + 1] = fmap(__uint_as_float(v.y));
        srow[i * 4 + 2] = fmap(__uint_as_float(v.z));
        srow[i * 4 + 3] = fmap(__uint_as_float(v.w));
    }
    for (int i = tid; i < DD; i += 512) xs[i] = x[(size_t)row * DD + i];
    if (tid == 0) { s_prefix = 0u; s_kk = TOPK; s_A = 0; s_cnt = 0; }
    __syncthreads();

    // exact radix select with PARALLEL suffix-scan bucket pick
    uint32_t maskhi = 0u;
    for (int b = 3; b >= 0; b--) {
        if (tid < 256) hist[tid] = 0u;
        __syncthreads();
        const uint32_t pref = s_prefix;
        const uint32_t kk = s_kk;
        const int sh = 8 * b;
        for (int i = tid; i < NN; i += 512) {
            uint32_t u = srow[i];
            if ((u & maskhi) == pref) atomicAdd(&hist[(u >> sh) & 0xFF], 1u);
        }
        __syncthreads();
        // suffix sum: hist[v] := sum_{u>=v} hist[u]
#pragma unroll
        for (int o = 1; o < 256; o <<= 1) {
            uint32_t t = 0;
            if (tid < 256 && tid + o < 256) t = hist[tid + o];
            __syncthreads();
            if (tid < 256) hist[tid] += t;
            __syncthreads();
        }
        if (tid < 256) {
            uint32_t hi = hist[tid];
            uint32_t hi1 = (tid < 255) ? hist[tid + 1] : 0u;
            if (hi1 < kk && kk <= hi) {
                s_prefix = pref | ((uint32_t)tid << sh);
                s_kk = kk - hi1;
            }
        }
        __syncthreads();
        maskhi |= (0xFFu << (8 * b));
    }
    const float th2 = funmap(s_prefix);
    const float thhi = th2 + 3e-3f;
    const float thlo = th2 - 3e-3f;

    for (int i = tid; i < NN; i += 512) {
        float z = funmap(srow[i]);
        if (z > thhi) atomicAdd(&s_A, 1);
        else if (z >= thlo) {
            int p = atomicAdd(&s_cnt, 1);
            if (p < BANDCAP) bidx[p] = i;
        }
    }
    __syncthreads();
    const int cnt = min(s_cnt, BANDCAP);
    const int need = TOPK - s_A;

    // band z via fp32 Kahan dot (products exact: w in {-1,0,+1})
    const float scf = g_scale[0];
    for (int b = warp; b < cnt; b += 16) {
        const int j = bidx[b];
        const u16* q = g_Q1 + (size_t)j * DD;
        float s = 0.0f, comp = 0.0f;
        for (int k = lane; k < DD; k += 32) {
            float prod = xs[k] * __half2float(__ushort_as_half(q[k]));
            float y = prod - comp;
            float t = s + y;
            comp = (t - s) - y;
            s = t;
        }
        double ds = (double)s - (double)comp;
#pragma unroll
        for (int o = 16; o > 0; o >>= 1) ds += __shfl_down_sync(0xffffffffu, ds, o);
        if (lane == 0) bz[b] = ds * (double)scf + (double)b_syn[j];
    }
    __syncthreads();

    for (int b = tid; b < cnt; b += 512) {
        int rank = 0;
        double v = bz[b];
        for (int b2 = 0; b2 < cnt; b2++) rank += (bz[b2] > v);
        binc[b] = (rank < need) ? 1 : 0;
    }
    __syncthreads();

    u16* hrow = g_H1 + (size_t)row * NN;
    for (int i = tid; i < NN / 4; i += 512) {
        ushort4 p;
        u16* a = &p.x;
#pragma unroll
        for (int j = 0; j < 4; j++) {
            float z = funmap(srow[i * 4 + j]);
            float h = (z > thhi) ? fmaxf(z, 0.0f) : 0.0f;
            a[j] = __half_as_ushort(__float2half_rn(h));
        }
        reinterpret_cast<ushort4*>(hrow)[i] = p;
    }
    __syncthreads();
    for (int b = tid; b < cnt; b += 512) {
        int j = bidx[b];
        float z = funmap(srow[j]);
        float h = binc[b] ? fmaxf(z, 0.0f) : 0.0f;
        hrow[j] = __half_as_ushort(__float2half_rn(h));
    }
}

__global__ void k_ln(const float* __restrict__ gamma, const float* __restrict__ beta,
                     float* __restrict__ out) {
    __shared__ float ssum[256], ssq[256];
    const int row = blockIdx.x, t = threadIdx.x;
    const float4* xp = reinterpret_cast<const float4*>(g_XO + (size_t)row * DD);
    float4 v0 = xp[t], v1 = xp[t + 256];
    float s = v0.x + v0.y + v0.z + v0.w + v1.x + v1.y + v1.z + v1.w;
    float q = v0.x * v0.x + v0.y * v0.y + v0.z * v0.z + v0.w * v0.w +
              v1.x * v1.x + v1.y * v1.y + v1.z * v1.z + v1.w * v1.w;
    ssum[t] = s; ssq[t] = q; __syncthreads();
    for (int o = 128; o > 0; o >>= 1) {
        if (t < o) { ssum[t] += ssum[t + o]; ssq[t] += ssq[t + o]; }
        __syncthreads();
    }
    float mu  = ssum[0] * (1.0f / DD);
    float var = ssq[0] * (1.0f / DD) - mu * mu;
    float rs  = rsqrtf(var + 1e-5f);
    const float4* gp = reinterpret_cast<const float4*>(gamma);
    const float4* bp = reinterpret_cast<const float4*>(beta);
    float4 g0 = gp[t], g1 = gp[t + 256];
    float4 b0 = bp[t], b1 = bp[t + 256];
    float4 o0, o1;
    o0.x = (v0.x - mu) * rs * g0.x + b0.x; o0.y = (v0.y - mu) * rs * g0.y + b0.y;
    o0.z = (v0.z - mu) * rs * g0.z + b0.z; o0.w = (v0.w - mu) * rs * g0.w + b0.w;
    o1.x = (v1.x - mu) * rs * g1.x + b1.x; o1.y = (v1.y - mu) * rs * g1.y + b1.y;
    o1.z = (v1.z - mu) * rs * g1.z + b1.z; o1.w = (v1.w - mu) * rs * g1.w + b1.w;
    float4* op = reinterpret_cast<float4*>(out + (size_t)row * DD);
    op[t] = o0; op[t + 256] = o1;
}

// ---------------- launcher --------------------------------------------------
extern "C" void kernel_launch(void* const* d_in, const int* in_sizes, int n_in,
                              void* d_out, int out_size) {
    (void)in_sizes; (void)n_in; (void)out_size;
    const float* x     = (const float*)d_in[0];
    const float* W_syn = (const float*)d_in[1];
    const float* b_syn = (const float*)d_in[2];
    const float* W_out = (const float*)d_in[3];
    const float* b_out = (const float*)d_in[4];
    const float* gamma = (const float*)d_in[5];
    const float* beta  = (const float*)d_in[6];
    float* out = (float*)d_out;

    const int SM1 = 3 * (2 * 18432 + 36864);   // 221184 B
    const int SM2 = 3 * (1 * 18432 + 36864);   // 165888 B
    cudaFuncSetAttribute(k_gemm_hmma<0, 2>, cudaFuncAttributeMaxDynamicSharedMemorySize, SM1);
    cudaFuncSetAttribute(k_gemm_hmma<1, 1>, cudaFuncAttributeMaxDynamicSharedMemorySize, SM2);

    // 3 launches before GEMM1 -> ncu -s 5 -c 1 keeps capturing the GEMM.
    k_abs2<<<dim3(2048, 2), 256>>>(W_syn, W_out);
    k_finalize_scales<<<1, 256>>>();
    k_prep<<<49152, 256>>>((const float4*)W_syn, (const float4*)W_out, (const float4*)x);
    k_gemm_hmma<0, 2><<<dim3(32, 64), 512, SM1>>>(b_syn, nullptr);
    k_topk_repair<<<MM, 512>>>(x, b_syn);
    k_gemm_hmma<1, 1><<<dim3(8, 64), 512, SM2>>>(b_out, x);
    k_ln<<<MM, 256>>>(gamma, beta, out);
}

// round 16
// speedup vs baseline: 1.5127x; 1.0847x over previous
#include <cuda_runtime.h>
#include <cuda_bf16.h>
#include <cuda_fp16.h>
#include <cstdint>

#define MM 8192
#define DD 2048
#define NN 8192
#define TOPK 819
#define BANDCAP 192
typedef unsigned short u16;

__device__ double g_partial[4096];
__device__ float  g_scale[2];
__device__ __align__(16) u16   g_X1[(size_t)MM * DD];   // f16 limb1 of x
__device__ __align__(16) u16   g_X2[(size_t)MM * DD];   // f16 limb2 of x
__device__ __align__(16) u16   g_Q1[(size_t)NN * DD];   // ternary W_syn (f16)
__device__ __align__(16) u16   g_Q2[(size_t)DD * NN];   // ternary W_out (f16)
__device__ __align__(16) float g_Z [(size_t)MM * NN];
__device__ __align__(16) u16   g_H1[(size_t)MM * NN];   // hidden (f16)
__device__ __align__(16) float g_XO[(size_t)MM * DD];

__device__ __forceinline__ uint32_t smem_u32(const void* p) {
    uint32_t a;
    asm("{ .reg .u64 t; cvta.to.shared.u64 t, %1; cvt.u32.u64 %0, t; }" : "=r"(a) : "l"(p));
    return a;
}
#define CP_COMMIT() asm volatile("cp.async.commit_group;" ::: "memory")
#define CP_WAIT(n)  asm volatile("cp.async.wait_group %0;" :: "n"(n) : "memory")

__device__ __forceinline__ void ldsm4(uint32_t* r, uint32_t addr) {
    asm volatile("ldmatrix.sync.aligned.m8n8.x4.shared.b16 {%0,%1,%2,%3}, [%4];"
                 : "=r"(r[0]), "=r"(r[1]), "=r"(r[2]), "=r"(r[3]) : "r"(addr));
}
__device__ __forceinline__ void mma_f32(float* c, uint32_t a0, uint32_t a1,
                                        uint32_t a2, uint32_t a3,
                                        uint32_t b0, uint32_t b1) {
    asm volatile(
        "mma.sync.aligned.m16n8k16.row.col.f32.f16.f16.f32 "
        "{%0,%1,%2,%3}, {%4,%5,%6,%7}, {%8,%9}, {%0,%1,%2,%3};\n"
        : "+f"(c[0]), "+f"(c[1]), "+f"(c[2]), "+f"(c[3])
        : "r"(a0), "r"(a1), "r"(a2), "r"(a3), "r"(b0), "r"(b1));
}

// ---------------- prep (exactly 3 launches before GEMM1) -------------------
__global__ void k_abs2(const float* __restrict__ Wa, const float* __restrict__ Wb) {
    __shared__ double sd[256];
    const int which = blockIdx.y;
    const float* W = which ? Wb : Wa;
    size_t base = (size_t)blockIdx.x * 8192 + threadIdx.x;
    double s = 0.0;
#pragma unroll
    for (int i = 0; i < 32; i++) s += (double)fabsf(W[base + (size_t)i * 256]);
    sd[threadIdx.x] = s; __syncthreads();
    for (int o = 128; o > 0; o >>= 1) {
        if ((int)threadIdx.x < o) sd[threadIdx.x] += sd[threadIdx.x + o];
        __syncthreads();
    }
    if (threadIdx.x == 0) g_partial[which * 2048 + blockIdx.x] = sd[0];
}
__global__ void k_finalize_scales() {
    __shared__ double sd[256];
    for (int w = 0; w < 2; w++) {
        double s = 0.0;
        for (int i = threadIdx.x; i < 2048; i += 256) s += g_partial[w * 2048 + i];
        sd[threadIdx.x] = s; __syncthreads();
        for (int o = 128; o > 0; o >>= 1) {
            if ((int)threadIdx.x < o) sd[threadIdx.x] += sd[threadIdx.x + o];
            __syncthreads();
        }
        if (threadIdx.x == 0) g_scale[w] = (float)(sd[0] / 16777216.0);
        __syncthreads();
    }
}
__device__ __forceinline__ u16 tq1h(float w, float den) {
    float t = __fdiv_rn(w, den);
    float q = fmaxf(-1.0f, fminf(1.0f, rintf(t)));
    return __half_as_ushort(__float2half_rn(q));    // exact -1/0/+1 in f16
}
__global__ void k_prep(const float4* __restrict__ Wa, const float4* __restrict__ Wb,
                       const float4* __restrict__ x) {
    const int part = blockIdx.x >> 14;
    size_t i = ((size_t)(blockIdx.x & 16383)) * 256 + threadIdx.x;
    if (part < 2) {
        const float4* W = part ? Wb : Wa;
        float den = g_scale[part] + 1e-8f;
        float4 w = W[i];
        ushort4 q;
        q.x = tq1h(w.x, den); q.y = tq1h(w.y, den); q.z = tq1h(w.z, den); q.w = tq1h(w.w, den);
        reinterpret_cast<ushort4*>(part ? g_Q2 : g_Q1)[i] = q;
    } else {
        float4 v = x[i];
        float f[4] = {v.x, v.y, v.z, v.w};
        ushort4 p1, p2;
        u16* a1 = &p1.x; u16* a2 = &p2.x;
#pragma unroll
        for (int j = 0; j < 4; j++) {
            __half h1 = __float2half_rn(f[j]);
            float r1 = f[j] - __half2float(h1);
            a1[j] = __half_as_ushort(h1);
            a2[j] = __half_as_ushort(__float2half_rn(r1));
        }
        reinterpret_cast<ushort4*>(g_X1)[i] = p1;
        reinterpret_cast<ushort4*>(g_X2)[i] = p2;
    }
}

// ---------------- pipelined HMMA GEMM, k-step 64, 512 threads ---------------
// CTA 128(m) x NTILE(n), 16 warps (4m x 4n), k-step 64, 3-stage cp.async,
// 144B-pitch smem rows. B-fragment double buffer hides ldsm->MMA latency.
template<int GID, int NLIMB, int NTILE>
__global__ void __launch_bounds__(512) k_gemm_hmma(
    const float* __restrict__ bias, const float* __restrict__ xres) {
    constexpr int AT = 128 * 144;
    constexpr int BT = NTILE * 144;
    constexpr int STAGE = NLIMB * AT + BT;
    constexpr int Kdim = (GID == 0) ? DD : NN;
    constexpr int Nout = (GID == 0) ? NN : DD;
    constexpr int steps = Kdim >> 6;
    constexpr int NG = NTILE / 64;            // 16-n breg groups per warp

    extern __shared__ char sm[];
    const uint32_t smaddr = smem_u32(sm);
    const int tid = threadIdx.x;
    const int warp = tid >> 5, lane = tid & 31;
    const int wm = warp >> 2, wn = warp & 3;
    const int tr = lane >> 2, tc = lane & 3;
    const int m0 = blockIdx.y * 128, n0 = blockIdx.x * NTILE;

    const u16* At[2];
    if (GID == 0) { At[0] = g_X1; At[1] = g_X2; }
    else          { At[0] = g_H1; At[1] = g_H1; }
    const u16* Bq = (GID == 0) ? g_Q1 : g_Q2;
    float* Cout = (GID == 0) ? g_Z : g_XO;

    float acc[2][2 * NG][4];
#pragma unroll
    for (int a = 0; a < 2; a++)
#pragma unroll
        for (int b = 0; b < 2 * NG; b++)
#pragma unroll
            for (int c = 0; c < 4; c++) acc[a][b][c] = 0.0f;

    const uint32_t aoff = (uint32_t)((wm * 32 + (lane & 15)) * 144 + ((lane & 16) ? 16 : 0));
    const uint32_t boff = (uint32_t)((wn * (NTILE / 4) + (lane & 7) + ((lane & 16) ? 8 : 0)) * 144 +
                                     ((lane & 8) ? 16 : 0));

#define LOAD_STAGE(stbuf, kkelem)                                                     \
    do {                                                                              \
        _Pragma("unroll")                                                             \
        for (int l = 0; l < NLIMB; l++) {                                             \
            _Pragma("unroll")                                                         \
            for (int j = 0; j < 2; j++) {                                             \
                int c = tid + 512 * j;                                                \
                int row = c >> 3, col = (c & 7) * 16;                                 \
                uint32_t dst = smaddr + (stbuf) * STAGE + l * AT + row * 144 + col;   \
                const char* src = (const char*)(At[l] + (size_t)(m0 + row) * Kdim + (kkelem)) + col; \
                asm volatile("cp.async.cg.shared.global [%0], [%1], 16;" :: "r"(dst), "l"(src) : "memory"); \
            }                                                                         \
        }                                                                             \
        _Pragma("unroll")                                                             \
        for (int j = 0; j < NTILE / 64; j++) {                                        \
            int c = tid + 512 * j;                                                    \
            int row = c >> 3, col = (c & 7) * 16;                                     \
            uint32_t dst = smaddr + (stbuf) * STAGE + NLIMB * AT + row * 144 + col;   \
            const char* src = (const char*)(Bq + (size_t)(n0 + row) * Kdim + (kkelem)) + col; \
            asm volatile("cp.async.cg.shared.global [%0], [%1], 16;" :: "r"(dst), "l"(src) : "memory"); \
        }                                                                             \
    } while (0)

#pragma unroll
    for (int st = 0; st < 2; st++) {
        LOAD_STAGE(st, st * 64);
        CP_COMMIT();
    }

    for (int t = 0; t < steps; t++) {
        CP_WAIT(1);
        __syncthreads();
        if (t + 2 < steps) {
            const int st = (t + 2) % 3;
            LOAD_STAGE(st, (t + 2) * 64);
        }
        CP_COMMIT();

        const uint32_t sstage = smaddr + (t % 3) * STAGE;
        const uint32_t sB = sstage + NLIMB * AT;

        uint32_t breg[2][NG][4];
#pragma unroll
        for (int nb = 0; nb < NG; nb++)
            ldsm4(breg[0][nb], sB + boff + nb * 2304);
#pragma unroll
        for (int h = 0; h < 4; h++) {
            const int cur = h & 1, nxt = cur ^ 1;
            if (h < 3) {
#pragma unroll
                for (int nb = 0; nb < NG; nb++)
                    ldsm4(breg[nxt][nb], sB + boff + nb * 2304 + (h + 1) * 32);
            }
#pragma unroll
            for (int l = 0; l < NLIMB; l++) {
                uint32_t areg[2][4];
#pragma unroll
                for (int mt = 0; mt < 2; mt++)
                    ldsm4(areg[mt], sstage + l * AT + aoff + mt * 2304 + h * 32);
#pragma unroll
                for (int mt = 0; mt < 2; mt++)
#pragma unroll
                    for (int nt = 0; nt < 2 * NG; nt++)
                        mma_f32(acc[mt][nt], areg[mt][0], areg[mt][1], areg[mt][2], areg[mt][3],
                                breg[cur][nt >> 1][(nt & 1) * 2], breg[cur][nt >> 1][(nt & 1) * 2 + 1]);
            }
        }
    }
#undef LOAD_STAGE

    const float sc = g_scale[GID];
#pragma unroll
    for (int mt = 0; mt < 2; mt++) {
        int r = m0 + wm * 32 + mt * 16 + tr;
#pragma unroll
        for (int nt = 0; nt < 2 * NG; nt++) {
            int n = n0 + wn * (NTILE / 4) + nt * 8 + tc * 2;
            float2 bs = *reinterpret_cast<const float2*>(bias + n);
            float2 o0 = make_float2(fmaf(acc[mt][nt][0], sc, bs.x),
                                    fmaf(acc[mt][nt][1], sc, bs.y));
            float2 o1 = make_float2(fmaf(acc[mt][nt][2], sc, bs.x),
                                    fmaf(acc[mt][nt][3], sc, bs.y));
            if (GID == 1) {
                float2 x0 = *reinterpret_cast<const float2*>(xres + (size_t)r * Nout + n);
                float2 x1 = *reinterpret_cast<const float2*>(xres + (size_t)(r + 8) * Nout + n);
                o0.x += x0.x; o0.y += x0.y; o1.x += x1.x; o1.y += x1.y;
            }
            *reinterpret_cast<float2*>(Cout + (size_t)r * Nout + n)       = o0;
            *reinterpret_cast<float2*>(Cout + (size_t)(r + 8) * Nout + n) = o1;
        }
    }
}

// ------- top-k: parallel-scan radix select + fp32-Kahan band repair --------
__device__ __forceinline__ uint32_t fmap(float f) {
    uint32_t b = __float_as_uint(f);
    return (b & 0x80000000u) ? ~b : (b | 0x80000000u);
}
__device__ __forceinline__ float funmap(uint32_t u) {
    uint32_t bits = (u & 0x80000000u) ? (u ^ 0x80000000u) : ~u;
    return __uint_as_float(bits);
}
__global__ void __launch_bounds__(512) k_topk_repair(const float* __restrict__ x,
                                                     const float* __restrict__ b_syn) {
    __shared__ uint32_t srow[NN];
    __shared__ float    xs[DD];
    __shared__ uint32_t hist[256];
    __shared__ double   bz[BANDCAP];
    __shared__ int      bidx[BANDCAP];
    __shared__ unsigned char binc[BANDCAP];
    __shared__ uint32_t s_prefix, s_kk;
    __shared__ int      s_A, s_cnt;
    const int row = blockIdx.x, tid = threadIdx.x;
    const int warp = tid >> 5, lane = tid & 31;

    const uint4* zp = reinterpret_cast<const uint4*>(g_Z + (size_t)row * NN);
    for (int i = tid; i < NN / 4; i += 512) {
        uint4 v = zp[i];
        srow[i * 4 + 0] = fmap(__uint_as_float(v.x));
        srow[i * 4 + 1] = fmap(__uint_as_float(v.y));
        srow[i * 4 + 2] = fmap(__uint_as_float(v.z));
        srow[i * 4 + 3] = fmap(__uint_as_float(v.w));
    }
    for (int i = tid; i < DD; i += 512) xs[i] = x[(size_t)row * DD + i];
    if (tid == 0) { s_prefix = 0u; s_kk = TOPK; s_A = 0; s_cnt = 0; }
    __syncthreads();

    uint32_t maskhi = 0u;
    for (int b = 3; b >= 0; b--) {
        if (tid < 256) hist[tid] = 0u;
        __syncthreads();
        const uint32_t pref = s_prefix;
        const uint32_t kk = s_kk;
        const int sh = 8 * b;
        for (int i = tid; i < NN; i += 512) {
            uint32_t u = srow[i];
            if ((u & maskhi) == pref) atomicAdd(&hist[(u >> sh) & 0xFF], 1u);
        }
        __syncthreads();
#pragma unroll
        for (int o = 1; o < 256; o <<= 1) {
            uint32_t t = 0;
            if (tid < 256 && tid + o < 256) t = hist[tid + o];
            __syncthreads();
            if (tid < 256) hist[tid] += t;
            __syncthreads();
        }
        if (tid < 256) {
            uint32_t hi = hist[tid];
            uint32_t hi1 = (tid < 255) ? hist[tid + 1] : 0u;
            if (hi1 < kk && kk <= hi) {
                s_prefix = pref | ((uint32_t)tid << sh);
                s_kk = kk - hi1;
            }
        }
        __syncthreads();
        maskhi |= (0xFFu << (8 * b));
    }
    const float th2 = funmap(s_prefix);
    const float thhi = th2 + 3e-3f;
    const float thlo = th2 - 3e-3f;

    for (int i = tid; i < NN; i += 512) {
        float z = funmap(srow[i]);
        if (z > thhi) atomicAdd(&s_A, 1);
        else if (z >= thlo) {
            int p = atomicAdd(&s_cnt, 1);
            if (p < BANDCAP) bidx[p] = i;
        }
    }
    __syncthreads();
    const int cnt = min(s_cnt, BANDCAP);
    const int need = TOPK - s_A;

    const float scf = g_scale[0];
    for (int b = warp; b < cnt; b += 16) {
        const int j = bidx[b];
        const u16* q = g_Q1 + (size_t)j * DD;
        float s = 0.0f, comp = 0.0f;
        for (int k = lane; k < DD; k += 32) {
            float prod = xs[k] * __half2float(__ushort_as_half(q[k]));
            float y = prod - comp;
            float t = s + y;
            comp = (t - s) - y;
            s = t;
        }
        double ds = (double)s - (double)comp;
#pragma unroll
        for (int o = 16; o > 0; o >>= 1) ds += __shfl_down_sync(0xffffffffu, ds, o);
        if (lane == 0) bz[b] = ds * (double)scf + (double)b_syn[j];
    }
    __syncthreads();

    for (int b = tid; b < cnt; b += 512) {
        int rank = 0;
        double v = bz[b];
        for (int b2 = 0; b2 < cnt; b2++) rank += (bz[b2] > v);
        binc[b] = (rank < need) ? 1 : 0;
    }
    __syncthreads();

    u16* hrow = g_H1 + (size_t)row * NN;
    for (int i = tid; i < NN / 4; i += 512) {
        ushort4 p;
        u16* a = &p.x;
#pragma unroll
        for (int j = 0; j < 4; j++) {
            float z = funmap(srow[i * 4 + j]);
            float h = (z > thhi) ? fmaxf(z, 0.0f) : 0.0f;
            a[j] = __half_as_ushort(__float2half_rn(h));
        }
        reinterpret_cast<ushort4*>(hrow)[i] = p;
    }
    __syncthreads();
    for (int b = tid; b < cnt; b += 512) {
        int j = bidx[b];
        float z = funmap(srow[j]);
        float h = binc[b] ? fmaxf(z, 0.0f) : 0.0f;
        hrow[j] = __half_as_ushort(__float2half_rn(h));
    }
}

__global__ void k_ln(const float* __restrict__ gamma, const float* __restrict__ beta,
                     float* __restrict__ out) {
    __shared__ float ssum[256], ssq[256];
    const int row = blockIdx.x, t = threadIdx.x;
    const float4* xp = reinterpret_cast<const float4*>(g_XO + (size_t)row * DD);
    float4 v0 = xp[t], v1 = xp[t + 256];
    float s = v0.x + v0.y + v0.z + v0.w + v1.x + v1.y + v1.z + v1.w;
    float q = v0.x * v0.x + v0.y * v0.y + v0.z * v0.z + v0.w * v0.w +
              v1.x * v1.x + v1.y * v1.y + v1.z * v1.z + v1.w * v1.w;
    ssum[t] = s; ssq[t] = q; __syncthreads();
    for (int o = 128; o > 0; o >>= 1) {
        if (t < o) { ssum[t] += ssum[t + o]; ssq[t] += ssq[t + o]; }
        __syncthreads();
    }
    float mu  = ssum[0] * (1.0f / DD);
    float var = ssq[0] * (1.0f / DD) - mu * mu;
    float rs  = rsqrtf(var + 1e-5f);
    const float4* gp = reinterpret_cast<const float4*>(gamma);
    const float4* bp = reinterpret_cast<const float4*>(beta);
    float4 g0 = gp[t], g1 = gp[t + 256];
    float4 b0 = bp[t], b1 = bp[t + 256];
    float4 o0, o1;
    o0.x = (v0.x - mu) * rs * g0.x + b0.x; o0.y = (v0.y - mu) * rs * g0.y + b0.y;
    o0.z = (v0.z - mu) * rs * g0.z + b0.z; o0.w = (v0.w - mu) * rs * g0.w + b0.w;
    o1.x = (v1.x - mu) * rs * g1.x + b1.x; o1.y = (v1.y - mu) * rs * g1.y + b1.y;
    o1.z = (v1.z - mu) * rs * g1.z + b1.z; o1.w = (v1.w - mu) * rs * g1.w + b1.w;
    float4* op = reinterpret_cast<float4*>(out + (size_t)row * DD);
    op[t] = o0; op[t + 256] = o1;
}

// ---------------- launcher --------------------------------------------------
extern "C" void kernel_launch(void* const* d_in, const int* in_sizes, int n_in,
                              void* d_out, int out_size) {
    (void)in_sizes; (void)n_in; (void)out_size;
    const float* x     = (const float*)d_in[0];
    const float* W_syn = (const float*)d_in[1];
    const float* b_syn = (const float*)d_in[2];
    const float* W_out = (const float*)d_in[3];
    const float* b_out = (const float*)d_in[4];
    const float* gamma = (const float*)d_in[5];
    const float* beta  = (const float*)d_in[6];
    float* out = (float*)d_out;

    const int SM1 = 3 * (2 * 18432 + 36864);   // 221184 B
    const int SM2 = 3 * (1 * 18432 + 18432);   // 110592 B
    cudaFuncSetAttribute(k_gemm_hmma<0, 2, 256>, cudaFuncAttributeMaxDynamicSharedMemorySize, SM1);
    cudaFuncSetAttribute(k_gemm_hmma<1, 1, 128>, cudaFuncAttributeMaxDynamicSharedMemorySize, SM2);

    // 3 launches before GEMM1 -> ncu -s 5 -c 1 keeps capturing the GEMM.
    k_abs2<<<dim3(2048, 2), 256>>>(W_syn, W_out);
    k_finalize_scales<<<1, 256>>>();
    k_prep<<<49152, 256>>>((const float4*)W_syn, (const float4*)W_out, (const float4*)x);
    k_gemm_hmma<0, 2, 256><<<dim3(32, 64), 512, SM1>>>(b_syn, nullptr);
    k_topk_repair<<<MM, 512>>>(x, b_syn);
    k_gemm_hmma<1, 1, 128><<<dim3(16, 64), 512, SM2>>>(b_out, x);
    k_ln<<<MM, 256>>>(gamma, beta, out);
}